// round 11
// baseline (speedup 1.0000x reference)
#include <cuda_runtime.h>
#include <cuda_fp16.h>

// ---------------- problem constants (fixed by the dataset) ----------------
#define MAXN 100000
#define MAXE 1600000
#define HID 64

// ---------------- device scratch (no allocation allowed) ------------------
__device__ __half d_h[MAXN * HID];     // h (gather source)
__device__ __half d_g[MAXN * HID];     // agg output / next GEMM input
__device__ float d_dis[MAXN];          // deg^{-1/2}
__device__ int   d_cnt[MAXN];          // in-degree; ALWAYS zero between launches
__device__ int   d_off[MAXN + 1];      // CSR offsets
__device__ int   d_cursor[MAXN];       // fill cursors
__device__ int   d_csrc[MAXE];         // CSR: src node per incoming edge slot
__device__ int   d_partials[128];      // scan block partials
__device__ int   d_done;               // blocksum completion counter (zero between launches)

// ---------------- packed fp32x2 helpers (Blackwell) ------------------------
__device__ __forceinline__ float2 ffma2(float2 a, float2 b, float2 c) {
    float2 d;
    asm("fma.rn.f32x2 %0, %1, %2, %3;"
        : "=l"(reinterpret_cast<unsigned long long&>(d))
        : "l"(reinterpret_cast<unsigned long long&>(a)),
          "l"(reinterpret_cast<unsigned long long&>(b)),
          "l"(reinterpret_cast<unsigned long long&>(c)));
    return d;
}
__device__ __forceinline__ float2 fadd2(float2 a, float2 b) {
    float2 d;
    asm("add.rn.f32x2 %0, %1, %2;"
        : "=l"(reinterpret_cast<unsigned long long&>(d))
        : "l"(reinterpret_cast<unsigned long long&>(a)),
          "l"(reinterpret_cast<unsigned long long&>(b)));
    return d;
}
__device__ __forceinline__ float4 fadd4(float4 a, float4 b) {
    float2 lo = fadd2(make_float2(a.x, a.y), make_float2(b.x, b.y));
    float2 hi = fadd2(make_float2(a.z, a.w), make_float2(b.z, b.w));
    return make_float4(lo.x, lo.y, hi.x, hi.y);
}
__device__ __forceinline__ float4 ffma4s(float s, float4 v, float4 c) {
    float2 sv = make_float2(s, s);
    float2 lo = ffma2(make_float2(v.x, v.y), sv, make_float2(c.x, c.y));
    float2 hi = ffma2(make_float2(v.z, v.w), sv, make_float2(c.z, c.w));
    return make_float4(lo.x, lo.y, hi.x, hi.y);
}

// ---------------- per-block index-dtype detection --------------------------
// edge_index values are uniform in [0, N). int64 words are all < N; int32
// pairs alias to huge words with p~1e-5 per word; 16 words -> certain.
// Returns via shared flag; call from ALL threads of the block.
__device__ __forceinline__ int block_detect_is64(const void* __restrict__ ei,
                                                 int* s_flag) {
    if (threadIdx.x == 0) {
        const long long* p = (const long long*)ei;
        int ok = 1;
#pragma unroll
        for (int k = 0; k < 16; k++) {
            long long v = p[k];
            if (v < 0 || v >= MAXN) ok = 0;
        }
        *s_flag = ok;
    }
    __syncthreads();
    return *s_flag;
}

__device__ __forceinline__ int load_idx64(const void* p, long long i, int is64) {
    return is64 ? (int)((const long long*)p)[i] : ((const int*)p)[i];
}
__device__ __forceinline__ long long load_batch64(const void* p, int i, int is64) {
    return is64 ? ((const long long*)p)[i] : (long long)((const int*)p)[i];
}

// ---------------- CSR build ------------------------------------------------
// d_cnt guaranteed zero on entry (zero-init at load; re-zeroed by k_scanblock)
__global__ void k_count(const void* __restrict__ ei, int E) {
    __shared__ int s_is64;
    int is64 = block_detect_is64(ei, &s_is64);
    int e = blockIdx.x * blockDim.x + threadIdx.x;
    if (e < E) {
        int dst = load_idx64(ei, (long long)E + e, is64);
        atomicAdd(&d_cnt[dst], 1);
    }
}

// per-1024 block sums + dis = rsqrt(deg+1); LAST block scans the <=128
// partials into exclusive block offsets (fence + done-counter pattern).
__global__ void k_blocksum(int N, int E, int nb) {
    __shared__ int sh[256];
    __shared__ int s_last;
    int b = blockIdx.x, t = threadIdx.x;
    int base = b * 1024;
    int s = 0;
#pragma unroll
    for (int i = 0; i < 4; i++) {
        int idx = base + t + i * 256;
        if (idx < N) {
            int c = d_cnt[idx];
            s += c;
            d_dis[idx] = rsqrtf((float)(c + 1));
        }
    }
    sh[t] = s;
    __syncthreads();
    for (int o = 128; o > 0; o >>= 1) {
        if (t < o) sh[t] += sh[t + o];
        __syncthreads();
    }
    if (t == 0) {
        d_partials[b] = sh[0];
        __threadfence();
        int prev = atomicAdd(&d_done, 1);
        s_last = (prev == nb - 1);
    }
    __syncthreads();
    if (!s_last) return;

    // last block: exclusive scan of nb (<=128) partials
    volatile int* vp = d_partials;
    int v = (t < nb) ? vp[t] : 0;
    __syncthreads();          // sh reuse
    sh[t] = (t < 128) ? v : 0;
    __syncthreads();
    for (int o = 1; o < 128; o <<= 1) {
        int u = (t >= o && t < 128) ? sh[t - o] : 0;
        __syncthreads();
        if (t < 128) sh[t] += u;
        __syncthreads();
    }
    if (t < nb) d_partials[t] = (t == 0) ? 0 : sh[t - 1];
    if (t == 0) {
        d_off[N] = E;
        d_done = 0;           // restore invariant for next replay
    }
}

// per-block 1024-wide scan -> CSR offsets + cursors; re-zeroes d_cnt
__global__ void k_scanblock(int N) {
    __shared__ int sh[1024];
    int b = blockIdx.x, t = threadIdx.x;
    int gid = b * 1024 + t;
    int v = (gid < N) ? d_cnt[gid] : 0;
    sh[t] = v;
    __syncthreads();
    for (int o = 1; o < 1024; o <<= 1) {
        int u = (t >= o) ? sh[t - o] : 0;
        __syncthreads();
        sh[t] += u;
        __syncthreads();
    }
    if (gid < N) {
        int excl = sh[t] - v + d_partials[b];
        d_off[gid] = excl;
        d_cursor[gid] = excl;
        d_cnt[gid] = 0;           // restore invariant
    }
}

__global__ void k_fill(const void* __restrict__ ei, int E) {
    __shared__ int s_is64;
    int is64 = block_detect_is64(ei, &s_is64);
    int e = blockIdx.x * blockDim.x + threadIdx.x;
    if (e < E) {
        int dst = load_idx64(ei, (long long)E + e, is64);
        int src = load_idx64(ei, e, is64);
        int p = atomicAdd(&d_cursor[dst], 1);
        d_csrc[p] = src;
    }
}

// ---------------- GEMM -----------------------------------------------------
// d_h[row] = half( (prescale ? dis[row] : 1) * (A[row] @ B) ), B: K x 64.
// BM=128, BN=64, BK=16; 256 threads; double-buffered smem; f32x2 math.
__global__ __launch_bounds__(256) void k_gemm(const float* __restrict__ Aext,
                                              const int half_in,
                                              const int prescale,
                                              const float* __restrict__ B,
                                              int N, int K) {
    __shared__ float As[2][16][128];
    __shared__ float Bs[2][16][64];
    int block_row = blockIdx.x * 128;
    int t = threadIdx.x;
    int tx = t & 15;
    int ty = t >> 4;
    int nc = K >> 4;

    int am = t >> 1;
    int ak = (t & 1) * 8;
    long long arow = block_row + am;
    int bk = t >> 4;
    int bn = (t & 15) * 4;

    float a_reg[8];
    float4 b_reg;

    auto load_regs = [&](int kc) {
        if (arow < N) {
            if (half_in) {
                uint4 raw = *(const uint4*)&d_g[arow * 64 + kc + ak];
                float2 f0 = __half22float2(*(__half2*)&raw.x);
                float2 f1 = __half22float2(*(__half2*)&raw.y);
                float2 f2 = __half22float2(*(__half2*)&raw.z);
                float2 f3 = __half22float2(*(__half2*)&raw.w);
                a_reg[0] = f0.x; a_reg[1] = f0.y;
                a_reg[2] = f1.x; a_reg[3] = f1.y;
                a_reg[4] = f2.x; a_reg[5] = f2.y;
                a_reg[6] = f3.x; a_reg[7] = f3.y;
            } else {
                float4 v0 = *(const float4*)&Aext[arow * K + kc + ak];
                float4 v1 = *(const float4*)&Aext[arow * K + kc + ak + 4];
                a_reg[0] = v0.x; a_reg[1] = v0.y; a_reg[2] = v0.z; a_reg[3] = v0.w;
                a_reg[4] = v1.x; a_reg[5] = v1.y; a_reg[6] = v1.z; a_reg[7] = v1.w;
            }
        } else {
#pragma unroll
            for (int i = 0; i < 8; i++) a_reg[i] = 0.f;
        }
        b_reg = *(const float4*)&B[(kc + bk) * 64 + bn];
    };
    auto sts = [&](int buf) {
#pragma unroll
        for (int i = 0; i < 8; i++) As[buf][ak + i][am] = a_reg[i];
        *(float4*)&Bs[buf][bk][bn] = b_reg;
    };

    float2 acc[4][4];
#pragma unroll
    for (int c = 0; c < 4; c++)
#pragma unroll
        for (int rp = 0; rp < 4; rp++) acc[c][rp] = make_float2(0.f, 0.f);

    load_regs(0);
    sts(0);
    __syncthreads();

    for (int c = 0; c < nc; c++) {
        if (c + 1 < nc) load_regs((c + 1) * 16);
        int buf = c & 1;
#pragma unroll
        for (int kk = 0; kk < 16; kk++) {
            float4 alo = *(float4*)&As[buf][kk][ty * 8];
            float4 ahi = *(float4*)&As[buf][kk][ty * 8 + 4];
            float2 a2[4] = {{alo.x, alo.y}, {alo.z, alo.w},
                            {ahi.x, ahi.y}, {ahi.z, ahi.w}};
            float4 b4 = *(float4*)&Bs[buf][kk][tx * 4];
            float bb[4] = {b4.x, b4.y, b4.z, b4.w};
#pragma unroll
            for (int cc = 0; cc < 4; cc++) {
                float2 bc = make_float2(bb[cc], bb[cc]);
#pragma unroll
                for (int rp = 0; rp < 4; rp++)
                    acc[cc][rp] = ffma2(a2[rp], bc, acc[cc][rp]);
            }
        }
        if (c + 1 < nc) {
            sts((c + 1) & 1);
            __syncthreads();
        }
    }

#pragma unroll
    for (int r = 0; r < 8; r++) {
        int row = block_row + ty * 8 + r;
        if (row < N) {
            float s = prescale ? d_dis[row] : 1.0f;
            int rp = r >> 1;
            float4 o;
            if (r & 1) {
                o.x = s * acc[0][rp].y; o.y = s * acc[1][rp].y;
                o.z = s * acc[2][rp].y; o.w = s * acc[3][rp].y;
            } else {
                o.x = s * acc[0][rp].x; o.y = s * acc[1][rp].x;
                o.z = s * acc[2][rp].x; o.w = s * acc[3][rp].x;
            }
            __half2 p0 = __floats2half2_rn(o.x, o.y);
            __half2 p1 = __floats2half2_rn(o.z, o.w);
            uint2 st;
            st.x = *(unsigned*)&p0;
            st.y = *(unsigned*)&p1;
            *(uint2*)&d_h[(long long)row * 64 + tx * 4] = st;
        }
    }
}

// ---------------- aggregation (prescaled input) ----------------------------
// d_g[i] = half( dis[i]*(h'[i] + sum_j h'[j]) + bias )  (+relu)
__global__ __launch_bounds__(256) void k_agg(const float* __restrict__ bias,
                                             int N, const int do_relu) {
    int node = blockIdx.x * 8 + (threadIdx.x >> 5);
    if (node >= N) return;
    int lane = threadIdx.x & 31;
    int half = lane >> 4;
    int fc = (lane & 15) * 4;

    float4 acc = make_float4(0.f, 0.f, 0.f, 0.f);
    int j = __ldg(&d_off[node]);
    int jend = __ldg(&d_off[node + 1]);

    for (; j + 8 <= jend; j += 8) {
        int sA = __ldg(&d_csrc[j + 0 + half]);
        int sB = __ldg(&d_csrc[j + 2 + half]);
        int sC = __ldg(&d_csrc[j + 4 + half]);
        int sD = __ldg(&d_csrc[j + 6 + half]);
        uint2 rA = __ldg((const uint2*)&d_h[(long long)sA * 64 + fc]);
        uint2 rB = __ldg((const uint2*)&d_h[(long long)sB * 64 + fc]);
        uint2 rC = __ldg((const uint2*)&d_h[(long long)sC * 64 + fc]);
        uint2 rD = __ldg((const uint2*)&d_h[(long long)sD * 64 + fc]);
        float2 aL = __half22float2(*(__half2*)&rA.x);
        float2 aH = __half22float2(*(__half2*)&rA.y);
        float2 bL = __half22float2(*(__half2*)&rB.x);
        float2 bH = __half22float2(*(__half2*)&rB.y);
        float2 cL = __half22float2(*(__half2*)&rC.x);
        float2 cH = __half22float2(*(__half2*)&rC.y);
        float2 dL = __half22float2(*(__half2*)&rD.x);
        float2 dH = __half22float2(*(__half2*)&rD.y);
        float4 t0 = make_float4(aL.x + bL.x, aL.y + bL.y, aH.x + bH.x, aH.y + bH.y);
        float4 t1 = make_float4(cL.x + dL.x, cL.y + dL.y, cH.x + dH.x, cH.y + dH.y);
        acc = fadd4(acc, fadd4(t0, t1));
    }
    for (; j + 2 <= jend; j += 2) {
        int s = __ldg(&d_csrc[j + half]);
        uint2 r = __ldg((const uint2*)&d_h[(long long)s * 64 + fc]);
        float2 lo = __half22float2(*(__half2*)&r.x);
        float2 hi = __half22float2(*(__half2*)&r.y);
        acc = fadd4(acc, make_float4(lo.x, lo.y, hi.x, hi.y));
    }
    if (j < jend && half == 0) {
        int s = __ldg(&d_csrc[j]);
        uint2 r = __ldg((const uint2*)&d_h[(long long)s * 64 + fc]);
        float2 lo = __half22float2(*(__half2*)&r.x);
        float2 hi = __half22float2(*(__half2*)&r.y);
        acc = fadd4(acc, make_float4(lo.x, lo.y, hi.x, hi.y));
    }

    acc.x += __shfl_xor_sync(0xffffffffu, acc.x, 16);
    acc.y += __shfl_xor_sync(0xffffffffu, acc.y, 16);
    acc.z += __shfl_xor_sync(0xffffffffu, acc.z, 16);
    acc.w += __shfl_xor_sync(0xffffffffu, acc.w, 16);

    if (half == 0) {
        uint2 rs = __ldg((const uint2*)&d_h[(long long)node * 64 + fc]);
        float2 slo = __half22float2(*(__half2*)&rs.x);
        float2 shi = __half22float2(*(__half2*)&rs.y);
        float di = d_dis[node];
        float4 b = __ldg((const float4*)&bias[fc]);
        float4 o;
        o.x = fmaf(di, acc.x + slo.x, b.x);
        o.y = fmaf(di, acc.y + slo.y, b.y);
        o.z = fmaf(di, acc.z + shi.x, b.z);
        o.w = fmaf(di, acc.w + shi.y, b.w);
        if (do_relu) {
            o.x = fmaxf(o.x, 0.f);
            o.y = fmaxf(o.y, 0.f);
            o.z = fmaxf(o.z, 0.f);
            o.w = fmaxf(o.w, 0.f);
        }
        __half2 q0 = __floats2half2_rn(o.x, o.y);
        __half2 q1 = __floats2half2_rn(o.z, o.w);
        uint2 st;
        st.x = *(unsigned*)&q0;
        st.y = *(unsigned*)&q1;
        *(uint2*)&d_g[(long long)node * 64 + fc] = st;
    }
}

// ---------------- weighted aggregation (UNprescaled input, conv1) ----------
// d_g[i] = half( dis[i]*(dis[i]*h[i] + sum_j dis[j]*h[j]) + bias )  (+relu)
__global__ __launch_bounds__(256) void k_aggw(const float* __restrict__ bias,
                                              int N, const int do_relu) {
    int node = blockIdx.x * 8 + (threadIdx.x >> 5);
    if (node >= N) return;
    int lane = threadIdx.x & 31;
    int half = lane >> 4;
    int fc = (lane & 15) * 4;

    float4 acc = make_float4(0.f, 0.f, 0.f, 0.f);
    int j = __ldg(&d_off[node]);
    int jend = __ldg(&d_off[node + 1]);

    for (; j + 8 <= jend; j += 8) {
        int sA = __ldg(&d_csrc[j + 0 + half]);
        int sB = __ldg(&d_csrc[j + 2 + half]);
        int sC = __ldg(&d_csrc[j + 4 + half]);
        int sD = __ldg(&d_csrc[j + 6 + half]);
        float wA = __ldg(&d_dis[sA]);
        float wB = __ldg(&d_dis[sB]);
        float wC = __ldg(&d_dis[sC]);
        float wD = __ldg(&d_dis[sD]);
        uint2 rA = __ldg((const uint2*)&d_h[(long long)sA * 64 + fc]);
        uint2 rB = __ldg((const uint2*)&d_h[(long long)sB * 64 + fc]);
        uint2 rC = __ldg((const uint2*)&d_h[(long long)sC * 64 + fc]);
        uint2 rD = __ldg((const uint2*)&d_h[(long long)sD * 64 + fc]);
        float2 aL = __half22float2(*(__half2*)&rA.x);
        float2 aH = __half22float2(*(__half2*)&rA.y);
        float2 bL = __half22float2(*(__half2*)&rB.x);
        float2 bH = __half22float2(*(__half2*)&rB.y);
        float2 cL = __half22float2(*(__half2*)&rC.x);
        float2 cH = __half22float2(*(__half2*)&rC.y);
        float2 dL = __half22float2(*(__half2*)&rD.x);
        float2 dH = __half22float2(*(__half2*)&rD.y);
        acc = ffma4s(wA, make_float4(aL.x, aL.y, aH.x, aH.y), acc);
        acc = ffma4s(wB, make_float4(bL.x, bL.y, bH.x, bH.y), acc);
        acc = ffma4s(wC, make_float4(cL.x, cL.y, cH.x, cH.y), acc);
        acc = ffma4s(wD, make_float4(dL.x, dL.y, dH.x, dH.y), acc);
    }
    for (; j + 2 <= jend; j += 2) {
        int s = __ldg(&d_csrc[j + half]);
        float w = __ldg(&d_dis[s]);
        uint2 r = __ldg((const uint2*)&d_h[(long long)s * 64 + fc]);
        float2 lo = __half22float2(*(__half2*)&r.x);
        float2 hi = __half22float2(*(__half2*)&r.y);
        acc = ffma4s(w, make_float4(lo.x, lo.y, hi.x, hi.y), acc);
    }
    if (j < jend && half == 0) {
        int s = __ldg(&d_csrc[j]);
        float w = __ldg(&d_dis[s]);
        uint2 r = __ldg((const uint2*)&d_h[(long long)s * 64 + fc]);
        float2 lo = __half22float2(*(__half2*)&r.x);
        float2 hi = __half22float2(*(__half2*)&r.y);
        acc = ffma4s(w, make_float4(lo.x, lo.y, hi.x, hi.y), acc);
    }

    acc.x += __shfl_xor_sync(0xffffffffu, acc.x, 16);
    acc.y += __shfl_xor_sync(0xffffffffu, acc.y, 16);
    acc.z += __shfl_xor_sync(0xffffffffu, acc.z, 16);
    acc.w += __shfl_xor_sync(0xffffffffu, acc.w, 16);

    if (half == 0) {
        float di = d_dis[node];
        uint2 rs = __ldg((const uint2*)&d_h[(long long)node * 64 + fc]);
        float2 slo = __half22float2(*(__half2*)&rs.x);
        float2 shi = __half22float2(*(__half2*)&rs.y);
        float4 self = make_float4(di * slo.x, di * slo.y, di * shi.x, di * shi.y);
        float4 b = __ldg((const float4*)&bias[fc]);
        float4 o;
        o.x = fmaf(di, acc.x + self.x, b.x);
        o.y = fmaf(di, acc.y + self.y, b.y);
        o.z = fmaf(di, acc.z + self.z, b.z);
        o.w = fmaf(di, acc.w + self.w, b.w);
        if (do_relu) {
            o.x = fmaxf(o.x, 0.f);
            o.y = fmaxf(o.y, 0.f);
            o.z = fmaxf(o.z, 0.f);
            o.w = fmaxf(o.w, 0.f);
        }
        __half2 q0 = __floats2half2_rn(o.x, o.y);
        __half2 q1 = __floats2half2_rn(o.z, o.w);
        uint2 st;
        st.x = *(unsigned*)&q0;
        st.y = *(unsigned*)&q1;
        *(uint2*)&d_g[(long long)node * 64 + fc] = st;
    }
}

// ---------------- pool + classifier fused ----------------------------------
__device__ __forceinline__ int lower_bound_b(const void* b, int N, long long v,
                                             int is64) {
    int lo = 0, hi = N;
    while (lo < hi) {
        int m = (lo + hi) >> 1;
        if (load_batch64(b, m, is64) < v) lo = m + 1; else hi = m;
    }
    return lo;
}

__global__ void k_poolcls(const void* __restrict__ batch,
                          const void* __restrict__ ei, int N,
                          const float* __restrict__ Wc1, const float* __restrict__ bc1,
                          const float* __restrict__ Wc2, const float* __restrict__ bc2,
                          float* __restrict__ out) {
    __shared__ int s_is64;
    int is64 = block_detect_is64(ei, &s_is64);   // batch shares ei's dtype
    int g = blockIdx.x;
    int start = lower_bound_b(batch, N, (long long)g, is64);
    int end = lower_bound_b(batch, N, (long long)g + 1, is64);
    int fc = (threadIdx.x & 15) * 4;
    int r = threadIdx.x >> 4;          // 0..15
    float4 acc = make_float4(0.f, 0.f, 0.f, 0.f);
    for (int i = start + r; i < end; i += 16) {
        uint2 raw = __ldg((const uint2*)&d_g[(long long)i * 64 + fc]);
        float2 lo = __half22float2(*(__half2*)&raw.x);
        float2 hi = __half22float2(*(__half2*)&raw.y);
        acc = fadd4(acc, make_float4(lo.x, lo.y, hi.x, hi.y));
    }
    __shared__ float4 sh[16][16];
    __shared__ float pm[64];
    sh[r][threadIdx.x & 15] = acc;
    __syncthreads();
    if (r == 0) {
        float4 v = sh[0][threadIdx.x & 15];
#pragma unroll
        for (int k = 1; k < 16; k++) {
            float4 u = sh[k][threadIdx.x & 15];
            v.x += u.x; v.y += u.y; v.z += u.z; v.w += u.w;
        }
        float inv = 1.0f / fmaxf((float)(end - start), 1.0f);
        pm[fc + 0] = v.x * inv;
        pm[fc + 1] = v.y * inv;
        pm[fc + 2] = v.z * inv;
        pm[fc + 3] = v.w * inv;
    }
    __syncthreads();
    if (threadIdx.x < 32) {
        int jj = threadIdx.x;
        float h = bc1[jj];
#pragma unroll
        for (int k = 0; k < 64; k++) h = fmaf(pm[k], __ldg(&Wc1[k * 32 + jj]), h);
        h = fmaxf(h, 0.f);
        float o0 = h * __ldg(&Wc2[jj * 2 + 0]);
        float o1 = h * __ldg(&Wc2[jj * 2 + 1]);
#pragma unroll
        for (int o = 16; o > 0; o >>= 1) {
            o0 += __shfl_down_sync(0xffffffffu, o0, o);
            o1 += __shfl_down_sync(0xffffffffu, o1, o);
        }
        if (jj == 0) {
            out[g * 2 + 0] = o0 + bc2[0];
            out[g * 2 + 1] = o1 + bc2[1];
        }
    }
}

// ---------------- launch ---------------------------------------------------
extern "C" void kernel_launch(void* const* d_in, const int* in_sizes, int n_in,
                              void* d_out, int out_size) {
    const float* x     = (const float*)d_in[0];
    const void*  ei    = d_in[1];
    const void*  batch = d_in[2];
    const float* W1 = (const float*)d_in[3];
    const float* b1 = (const float*)d_in[4];
    const float* W2 = (const float*)d_in[5];
    const float* b2 = (const float*)d_in[6];
    const float* W3 = (const float*)d_in[7];
    const float* b3 = (const float*)d_in[8];
    const float* Wc1 = (const float*)d_in[9];
    const float* bc1 = (const float*)d_in[10];
    const float* Wc2 = (const float*)d_in[11];
    const float* bc2 = (const float*)d_in[12];
    float* out = (float*)d_out;

    int N = in_sizes[0] / 128;
    int E = in_sizes[1] / 2;
    int G = out_size / 2;

    int nb = (N + 1023) / 1024;
    int gemm_blocks = (N + 127) / 128;
    int agg_blocks = (N + 7) / 8;

    // lazily created host-side objects (no device memory involved);
    // created on the first (correctness) call, before graph capture starts.
    static cudaStream_t s_gemm = nullptr;
    static cudaEvent_t ev_fork = nullptr, ev_join = nullptr;
    if (s_gemm == nullptr) {
        cudaStreamCreate(&s_gemm);
        cudaEventCreateWithFlags(&ev_fork, cudaEventDisableTiming);
        cudaEventCreateWithFlags(&ev_join, cudaEventDisableTiming);
    }

    // fork: GEMM1 (x @ W1, unprescaled) runs concurrent with the CSR build
    cudaEventRecord(ev_fork, 0);
    cudaStreamWaitEvent(s_gemm, ev_fork, 0);
    k_gemm<<<gemm_blocks, 256, 0, s_gemm>>>(x, 0, 0, W1, N, 128);
    cudaEventRecord(ev_join, s_gemm);

    // CSR build chain (d_cnt and d_done are zero on entry)
    k_count<<<(E + 255) / 256, 256>>>(ei, E);
    k_blocksum<<<nb, 256>>>(N, E, nb);
    k_scanblock<<<nb, 1024>>>(N);
    k_fill<<<(E + 255) / 256, 256>>>(ei, E);

    // join, then conv1 aggregation (weighted: input h is unprescaled)
    cudaStreamWaitEvent(0, ev_join, 0);
    k_aggw<<<agg_blocks, 256>>>(b1, N, 1);
    // conv2 (prescaled path)
    k_gemm<<<gemm_blocks, 256>>>(nullptr, 1, 1, W2, N, 64);
    k_agg<<<agg_blocks, 256>>>(b2, N, 1);
    // conv3 (no relu)
    k_gemm<<<gemm_blocks, 256>>>(nullptr, 1, 1, W3, N, 64);
    k_agg<<<agg_blocks, 256>>>(b3, N, 0);

    // fused pool + classifier
    k_poolcls<<<G, 256>>>(batch, ei, N, Wc1, bc1, Wc2, bc2, out);
}

// round 12
// speedup vs baseline: 1.1409x; 1.1409x over previous
#include <cuda_runtime.h>
#include <cuda_fp16.h>

// ---------------- problem constants (fixed by the dataset) ----------------
#define MAXN 100000
#define MAXE 1600000
#define HID 64

// ---------------- device scratch (no allocation allowed) ------------------
__device__ __half d_h[MAXN * HID];     // buffer 0
__device__ __half d_g[MAXN * HID];     // buffer 1
__device__ float d_dis[MAXN];          // deg^{-1/2}
__device__ int   d_cnt[MAXN];          // in-degree; ALWAYS zero between launches
__device__ int   d_off[MAXN + 1];      // CSR offsets
__device__ int   d_cursor[MAXN];       // fill cursors
__device__ int   d_csrc[MAXE];         // CSR: src node per incoming edge slot
__device__ int   d_partials[128];      // scan block partials
__device__ int   g_is64;               // 1 if index tensors are int64

// ---------------- packed fp32x2 helpers (Blackwell) ------------------------
__device__ __forceinline__ float2 ffma2(float2 a, float2 b, float2 c) {
    float2 d;
    asm("fma.rn.f32x2 %0, %1, %2, %3;"
        : "=l"(reinterpret_cast<unsigned long long&>(d))
        : "l"(reinterpret_cast<unsigned long long&>(a)),
          "l"(reinterpret_cast<unsigned long long&>(b)),
          "l"(reinterpret_cast<unsigned long long&>(c)));
    return d;
}
__device__ __forceinline__ float2 fadd2(float2 a, float2 b) {
    float2 d;
    asm("add.rn.f32x2 %0, %1, %2;"
        : "=l"(reinterpret_cast<unsigned long long&>(d))
        : "l"(reinterpret_cast<unsigned long long&>(a)),
          "l"(reinterpret_cast<unsigned long long&>(b)));
    return d;
}
__device__ __forceinline__ float4 fadd4(float4 a, float4 b) {
    float2 lo = fadd2(make_float2(a.x, a.y), make_float2(b.x, b.y));
    float2 hi = fadd2(make_float2(a.z, a.w), make_float2(b.z, b.w));
    return make_float4(lo.x, lo.y, hi.x, hi.y);
}
__device__ __forceinline__ float4 ffma4s(float s, float4 v, float4 c) {
    float2 sv = make_float2(s, s);
    float2 lo = ffma2(make_float2(v.x, v.y), sv, make_float2(c.x, c.y));
    float2 hi = ffma2(make_float2(v.z, v.w), sv, make_float2(c.z, c.w));
    return make_float4(lo.x, lo.y, hi.x, hi.y);
}

// ---------------- index helpers -------------------------------------------
__device__ __forceinline__ int load_idx(const void* p, long long i) {
    return g_is64 ? (int)((const long long*)p)[i] : ((const int*)p)[i];
}
__device__ __forceinline__ long long load_batch(const void* p, int i) {
    return g_is64 ? ((const long long*)p)[i] : (long long)((const int*)p)[i];
}

// ---------------- CSR build ------------------------------------------------
__global__ void k_detect(const void* __restrict__ ei) {
    const long long* p = (const long long*)ei;
    int ok = 1;
#pragma unroll
    for (int k = 0; k < 16; k++) {
        long long v = p[k];
        if (v < 0 || v >= MAXN) ok = 0;
    }
    g_is64 = ok;
}

// d_cnt guaranteed zero on entry (zero-init at load; re-zeroed by k_scanblock)
__global__ void k_count(const void* __restrict__ ei, int E) {
    int e = blockIdx.x * blockDim.x + threadIdx.x;
    if (e < E) {
        int dst = load_idx(ei, (long long)E + e);
        atomicAdd(&d_cnt[dst], 1);
    }
}

__global__ void k_blocksum(int N) {
    __shared__ int sh[256];
    int b = blockIdx.x, t = threadIdx.x;
    int base = b * 1024;
    int s = 0;
#pragma unroll
    for (int i = 0; i < 4; i++) {
        int idx = base + t + i * 256;
        if (idx < N) {
            int c = d_cnt[idx];
            s += c;
            d_dis[idx] = rsqrtf((float)(c + 1));
        }
    }
    sh[t] = s;
    __syncthreads();
    for (int o = 128; o > 0; o >>= 1) {
        if (t < o) sh[t] += sh[t + o];
        __syncthreads();
    }
    if (t == 0) d_partials[b] = sh[0];
}

__global__ void k_scanpart(int nb, int N, int E) {
    __shared__ int sh[128];
    int t = threadIdx.x;
    sh[t] = (t < nb) ? d_partials[t] : 0;
    __syncthreads();
    for (int o = 1; o < 128; o <<= 1) {
        int v = (t >= o) ? sh[t - o] : 0;
        __syncthreads();
        sh[t] += v;
        __syncthreads();
    }
    if (t < nb) d_partials[t] = (t == 0) ? 0 : sh[t - 1];
    if (t == 0) d_off[N] = E;
}

// per-block 1024-wide scan -> CSR offsets + cursors; re-zeroes d_cnt
__global__ void k_scanblock(int N) {
    __shared__ int sh[1024];
    int b = blockIdx.x, t = threadIdx.x;
    int gid = b * 1024 + t;
    int v = (gid < N) ? d_cnt[gid] : 0;
    sh[t] = v;
    __syncthreads();
    for (int o = 1; o < 1024; o <<= 1) {
        int u = (t >= o) ? sh[t - o] : 0;
        __syncthreads();
        sh[t] += u;
        __syncthreads();
    }
    if (gid < N) {
        int excl = sh[t] - v + d_partials[b];
        d_off[gid] = excl;
        d_cursor[gid] = excl;
        d_cnt[gid] = 0;           // restore invariant
    }
}

__global__ void k_fill(const void* __restrict__ ei, int E) {
    int e = blockIdx.x * blockDim.x + threadIdx.x;
    if (e < E) {
        int dst = load_idx(ei, (long long)E + e);
        int src = load_idx(ei, e);
        int p = atomicAdd(&d_cursor[dst], 1);
        d_csrc[p] = src;
    }
}

// ---------------- GEMM -----------------------------------------------------
// d_h[row] = half( (prescale ? dis[row] : 1) * (A[row] @ B) ), B: K x 64.
// BM=128, BN=64, BK=16; 256 threads; double-buffered smem; f32x2 math.
// half_in=0: A = Aext fp32 (stride K); half_in=1: A = d_g half (stride 64).
__global__ __launch_bounds__(256) void k_gemm(const float* __restrict__ Aext,
                                              const int half_in,
                                              const int prescale,
                                              const float* __restrict__ B,
                                              int N, int K) {
    __shared__ float As[2][16][128];
    __shared__ float Bs[2][16][64];
    int block_row = blockIdx.x * 128;
    int t = threadIdx.x;
    int tx = t & 15;
    int ty = t >> 4;
    int nc = K >> 4;

    int am = t >> 1;
    int ak = (t & 1) * 8;
    long long arow = block_row + am;
    int bk = t >> 4;
    int bn = (t & 15) * 4;

    float a_reg[8];
    float4 b_reg;

    auto load_regs = [&](int kc) {
        if (arow < N) {
            if (half_in) {
                uint4 raw = *(const uint4*)&d_g[arow * 64 + kc + ak];
                float2 f0 = __half22float2(*(__half2*)&raw.x);
                float2 f1 = __half22float2(*(__half2*)&raw.y);
                float2 f2 = __half22float2(*(__half2*)&raw.z);
                float2 f3 = __half22float2(*(__half2*)&raw.w);
                a_reg[0] = f0.x; a_reg[1] = f0.y;
                a_reg[2] = f1.x; a_reg[3] = f1.y;
                a_reg[4] = f2.x; a_reg[5] = f2.y;
                a_reg[6] = f3.x; a_reg[7] = f3.y;
            } else {
                float4 v0 = *(const float4*)&Aext[arow * K + kc + ak];
                float4 v1 = *(const float4*)&Aext[arow * K + kc + ak + 4];
                a_reg[0] = v0.x; a_reg[1] = v0.y; a_reg[2] = v0.z; a_reg[3] = v0.w;
                a_reg[4] = v1.x; a_reg[5] = v1.y; a_reg[6] = v1.z; a_reg[7] = v1.w;
            }
        } else {
#pragma unroll
            for (int i = 0; i < 8; i++) a_reg[i] = 0.f;
        }
        b_reg = *(const float4*)&B[(kc + bk) * 64 + bn];
    };
    auto sts = [&](int buf) {
#pragma unroll
        for (int i = 0; i < 8; i++) As[buf][ak + i][am] = a_reg[i];
        *(float4*)&Bs[buf][bk][bn] = b_reg;
    };

    float2 acc[4][4];
#pragma unroll
    for (int c = 0; c < 4; c++)
#pragma unroll
        for (int rp = 0; rp < 4; rp++) acc[c][rp] = make_float2(0.f, 0.f);

    load_regs(0);
    sts(0);
    __syncthreads();

    for (int c = 0; c < nc; c++) {
        if (c + 1 < nc) load_regs((c + 1) * 16);
        int buf = c & 1;
#pragma unroll
        for (int kk = 0; kk < 16; kk++) {
            float4 alo = *(float4*)&As[buf][kk][ty * 8];
            float4 ahi = *(float4*)&As[buf][kk][ty * 8 + 4];
            float2 a2[4] = {{alo.x, alo.y}, {alo.z, alo.w},
                            {ahi.x, ahi.y}, {ahi.z, ahi.w}};
            float4 b4 = *(float4*)&Bs[buf][kk][tx * 4];
            float bb[4] = {b4.x, b4.y, b4.z, b4.w};
#pragma unroll
            for (int cc = 0; cc < 4; cc++) {
                float2 bc = make_float2(bb[cc], bb[cc]);
#pragma unroll
                for (int rp = 0; rp < 4; rp++)
                    acc[cc][rp] = ffma2(a2[rp], bc, acc[cc][rp]);
            }
        }
        if (c + 1 < nc) {
            sts((c + 1) & 1);
            __syncthreads();
        }
    }

#pragma unroll
    for (int r = 0; r < 8; r++) {
        int row = block_row + ty * 8 + r;
        if (row < N) {
            float s = prescale ? d_dis[row] : 1.0f;
            int rp = r >> 1;
            float4 o;
            if (r & 1) {
                o.x = s * acc[0][rp].y; o.y = s * acc[1][rp].y;
                o.z = s * acc[2][rp].y; o.w = s * acc[3][rp].y;
            } else {
                o.x = s * acc[0][rp].x; o.y = s * acc[1][rp].x;
                o.z = s * acc[2][rp].x; o.w = s * acc[3][rp].x;
            }
            __half2 p0 = __floats2half2_rn(o.x, o.y);
            __half2 p1 = __floats2half2_rn(o.z, o.w);
            uint2 st;
            st.x = *(unsigned*)&p0;
            st.y = *(unsigned*)&p1;
            *(uint2*)&d_h[(long long)row * 64 + tx * 4] = st;
        }
    }
}

// ---------------- aggregation (prescaled input, generalized) ---------------
// o = dis[i]*(src[i] + sum_{j in N(i)} src[j]) + bias (if bias)   (+relu)
// if post_scale: o *= dis[i]   (prepares next layer's prescaled input)
// srcflag/dstflag: 0 = d_h, 1 = d_g
__global__ __launch_bounds__(256) void k_agg(const int srcflag, const int dstflag,
                                             const float* __restrict__ bias,
                                             int N, const int do_relu,
                                             const int post_scale) {
    const __half* hin = srcflag ? d_g : d_h;
    __half* hout = dstflag ? d_g : d_h;

    int node = blockIdx.x * 8 + (threadIdx.x >> 5);
    if (node >= N) return;
    int lane = threadIdx.x & 31;
    int half = lane >> 4;
    int fc = (lane & 15) * 4;

    float4 acc = make_float4(0.f, 0.f, 0.f, 0.f);
    int j = __ldg(&d_off[node]);
    int jend = __ldg(&d_off[node + 1]);

    for (; j + 8 <= jend; j += 8) {
        int sA = __ldg(&d_csrc[j + 0 + half]);
        int sB = __ldg(&d_csrc[j + 2 + half]);
        int sC = __ldg(&d_csrc[j + 4 + half]);
        int sD = __ldg(&d_csrc[j + 6 + half]);
        uint2 rA = __ldg((const uint2*)&hin[(long long)sA * 64 + fc]);
        uint2 rB = __ldg((const uint2*)&hin[(long long)sB * 64 + fc]);
        uint2 rC = __ldg((const uint2*)&hin[(long long)sC * 64 + fc]);
        uint2 rD = __ldg((const uint2*)&hin[(long long)sD * 64 + fc]);
        float2 aL = __half22float2(*(__half2*)&rA.x);
        float2 aH = __half22float2(*(__half2*)&rA.y);
        float2 bL = __half22float2(*(__half2*)&rB.x);
        float2 bH = __half22float2(*(__half2*)&rB.y);
        float2 cL = __half22float2(*(__half2*)&rC.x);
        float2 cH = __half22float2(*(__half2*)&rC.y);
        float2 dL = __half22float2(*(__half2*)&rD.x);
        float2 dH = __half22float2(*(__half2*)&rD.y);
        float4 t0 = make_float4(aL.x + bL.x, aL.y + bL.y, aH.x + bH.x, aH.y + bH.y);
        float4 t1 = make_float4(cL.x + dL.x, cL.y + dL.y, cH.x + dH.x, cH.y + dH.y);
        acc = fadd4(acc, fadd4(t0, t1));
    }
    for (; j + 2 <= jend; j += 2) {
        int s = __ldg(&d_csrc[j + half]);
        uint2 r = __ldg((const uint2*)&hin[(long long)s * 64 + fc]);
        float2 lo = __half22float2(*(__half2*)&r.x);
        float2 hi = __half22float2(*(__half2*)&r.y);
        acc = fadd4(acc, make_float4(lo.x, lo.y, hi.x, hi.y));
    }
    if (j < jend && half == 0) {
        int s = __ldg(&d_csrc[j]);
        uint2 r = __ldg((const uint2*)&hin[(long long)s * 64 + fc]);
        float2 lo = __half22float2(*(__half2*)&r.x);
        float2 hi = __half22float2(*(__half2*)&r.y);
        acc = fadd4(acc, make_float4(lo.x, lo.y, hi.x, hi.y));
    }

    acc.x += __shfl_xor_sync(0xffffffffu, acc.x, 16);
    acc.y += __shfl_xor_sync(0xffffffffu, acc.y, 16);
    acc.z += __shfl_xor_sync(0xffffffffu, acc.z, 16);
    acc.w += __shfl_xor_sync(0xffffffffu, acc.w, 16);

    if (half == 0) {
        uint2 rs = __ldg((const uint2*)&hin[(long long)node * 64 + fc]);
        float2 slo = __half22float2(*(__half2*)&rs.x);
        float2 shi = __half22float2(*(__half2*)&rs.y);
        float di = d_dis[node];
        float4 b = bias ? __ldg((const float4*)&bias[fc])
                        : make_float4(0.f, 0.f, 0.f, 0.f);
        float4 o;
        o.x = fmaf(di, acc.x + slo.x, b.x);
        o.y = fmaf(di, acc.y + slo.y, b.y);
        o.z = fmaf(di, acc.z + shi.x, b.z);
        o.w = fmaf(di, acc.w + shi.y, b.w);
        if (do_relu) {
            o.x = fmaxf(o.x, 0.f);
            o.y = fmaxf(o.y, 0.f);
            o.z = fmaxf(o.z, 0.f);
            o.w = fmaxf(o.w, 0.f);
        }
        if (post_scale) {
            o.x *= di; o.y *= di; o.z *= di; o.w *= di;
        }
        __half2 q0 = __floats2half2_rn(o.x, o.y);
        __half2 q1 = __floats2half2_rn(o.z, o.w);
        uint2 st;
        st.x = *(unsigned*)&q0;
        st.y = *(unsigned*)&q1;
        *(uint2*)&hout[(long long)node * 64 + fc] = st;
    }
}

// ---------------- weighted aggregation (UNprescaled input, conv1) ----------
// d_g[i] = half( dis[i]*(dis[i]*h[i] + sum_j dis[j]*h[j]) + bias )  (+relu)
__global__ __launch_bounds__(256) void k_aggw(const float* __restrict__ bias,
                                              int N, const int do_relu) {
    int node = blockIdx.x * 8 + (threadIdx.x >> 5);
    if (node >= N) return;
    int lane = threadIdx.x & 31;
    int half = lane >> 4;
    int fc = (lane & 15) * 4;

    float4 acc = make_float4(0.f, 0.f, 0.f, 0.f);
    int j = __ldg(&d_off[node]);
    int jend = __ldg(&d_off[node + 1]);

    for (; j + 8 <= jend; j += 8) {
        int sA = __ldg(&d_csrc[j + 0 + half]);
        int sB = __ldg(&d_csrc[j + 2 + half]);
        int sC = __ldg(&d_csrc[j + 4 + half]);
        int sD = __ldg(&d_csrc[j + 6 + half]);
        float wA = __ldg(&d_dis[sA]);
        float wB = __ldg(&d_dis[sB]);
        float wC = __ldg(&d_dis[sC]);
        float wD = __ldg(&d_dis[sD]);
        uint2 rA = __ldg((const uint2*)&d_h[(long long)sA * 64 + fc]);
        uint2 rB = __ldg((const uint2*)&d_h[(long long)sB * 64 + fc]);
        uint2 rC = __ldg((const uint2*)&d_h[(long long)sC * 64 + fc]);
        uint2 rD = __ldg((const uint2*)&d_h[(long long)sD * 64 + fc]);
        float2 aL = __half22float2(*(__half2*)&rA.x);
        float2 aH = __half22float2(*(__half2*)&rA.y);
        float2 bL = __half22float2(*(__half2*)&rB.x);
        float2 bH = __half22float2(*(__half2*)&rB.y);
        float2 cL = __half22float2(*(__half2*)&rC.x);
        float2 cH = __half22float2(*(__half2*)&rC.y);
        float2 dL = __half22float2(*(__half2*)&rD.x);
        float2 dH = __half22float2(*(__half2*)&rD.y);
        acc = ffma4s(wA, make_float4(aL.x, aL.y, aH.x, aH.y), acc);
        acc = ffma4s(wB, make_float4(bL.x, bL.y, bH.x, bH.y), acc);
        acc = ffma4s(wC, make_float4(cL.x, cL.y, cH.x, cH.y), acc);
        acc = ffma4s(wD, make_float4(dL.x, dL.y, dH.x, dH.y), acc);
    }
    for (; j + 2 <= jend; j += 2) {
        int s = __ldg(&d_csrc[j + half]);
        float w = __ldg(&d_dis[s]);
        uint2 r = __ldg((const uint2*)&d_h[(long long)s * 64 + fc]);
        float2 lo = __half22float2(*(__half2*)&r.x);
        float2 hi = __half22float2(*(__half2*)&r.y);
        acc = ffma4s(w, make_float4(lo.x, lo.y, hi.x, hi.y), acc);
    }
    if (j < jend && half == 0) {
        int s = __ldg(&d_csrc[j]);
        float w = __ldg(&d_dis[s]);
        uint2 r = __ldg((const uint2*)&d_h[(long long)s * 64 + fc]);
        float2 lo = __half22float2(*(__half2*)&r.x);
        float2 hi = __half22float2(*(__half2*)&r.y);
        acc = ffma4s(w, make_float4(lo.x, lo.y, hi.x, hi.y), acc);
    }

    acc.x += __shfl_xor_sync(0xffffffffu, acc.x, 16);
    acc.y += __shfl_xor_sync(0xffffffffu, acc.y, 16);
    acc.z += __shfl_xor_sync(0xffffffffu, acc.z, 16);
    acc.w += __shfl_xor_sync(0xffffffffu, acc.w, 16);

    if (half == 0) {
        float di = d_dis[node];
        uint2 rs = __ldg((const uint2*)&d_h[(long long)node * 64 + fc]);
        float2 slo = __half22float2(*(__half2*)&rs.x);
        float2 shi = __half22float2(*(__half2*)&rs.y);
        float4 self = make_float4(di * slo.x, di * slo.y, di * shi.x, di * shi.y);
        float4 b = __ldg((const float4*)&bias[fc]);
        float4 o;
        o.x = fmaf(di, acc.x + self.x, b.x);
        o.y = fmaf(di, acc.y + self.y, b.y);
        o.z = fmaf(di, acc.z + self.z, b.z);
        o.w = fmaf(di, acc.w + self.w, b.w);
        if (do_relu) {
            o.x = fmaxf(o.x, 0.f);
            o.y = fmaxf(o.y, 0.f);
            o.z = fmaxf(o.z, 0.f);
            o.w = fmaxf(o.w, 0.f);
        }
        __half2 q0 = __floats2half2_rn(o.x, o.y);
        __half2 q1 = __floats2half2_rn(o.z, o.w);
        uint2 st;
        st.x = *(unsigned*)&q0;
        st.y = *(unsigned*)&q1;
        *(uint2*)&d_g[(long long)node * 64 + fc] = st;
    }
}

// ---------------- pool + W3/b3 + classifier fused ---------------------------
// reads pre-W3 features (Â h2) from d_h; pooled = mean(Â h2) @ W3 + b3;
// then 2-layer classifier MLP.
__device__ __forceinline__ int lower_bound_b(const void* b, int N, long long v) {
    int lo = 0, hi = N;
    while (lo < hi) {
        int m = (lo + hi) >> 1;
        if (load_batch(b, m) < v) lo = m + 1; else hi = m;
    }
    return lo;
}

__global__ void k_poolcls(const void* __restrict__ batch, int N,
                          const float* __restrict__ W3, const float* __restrict__ b3,
                          const float* __restrict__ Wc1, const float* __restrict__ bc1,
                          const float* __restrict__ Wc2, const float* __restrict__ bc2,
                          float* __restrict__ out) {
    int g = blockIdx.x;
    int start = lower_bound_b(batch, N, (long long)g);
    int end = lower_bound_b(batch, N, (long long)g + 1);
    int fc = (threadIdx.x & 15) * 4;
    int r = threadIdx.x >> 4;          // 0..15
    float4 acc = make_float4(0.f, 0.f, 0.f, 0.f);
    for (int i = start + r; i < end; i += 16) {
        uint2 raw = __ldg((const uint2*)&d_h[(long long)i * 64 + fc]);
        float2 lo = __half22float2(*(__half2*)&raw.x);
        float2 hi = __half22float2(*(__half2*)&raw.y);
        acc = fadd4(acc, make_float4(lo.x, lo.y, hi.x, hi.y));
    }
    __shared__ float4 sh[16][16];
    __shared__ float praw[64];   // mean(Â h2)
    __shared__ float pm[64];     // praw @ W3 + b3
    sh[r][threadIdx.x & 15] = acc;
    __syncthreads();
    if (r == 0) {
        float4 v = sh[0][threadIdx.x & 15];
#pragma unroll
        for (int k = 1; k < 16; k++) {
            float4 u = sh[k][threadIdx.x & 15];
            v.x += u.x; v.y += u.y; v.z += u.z; v.w += u.w;
        }
        float inv = 1.0f / fmaxf((float)(end - start), 1.0f);
        praw[fc + 0] = v.x * inv;
        praw[fc + 1] = v.y * inv;
        praw[fc + 2] = v.z * inv;
        praw[fc + 3] = v.w * inv;
    }
    __syncthreads();
    // apply W3/b3 on the pooled vector (64x64 tiny GEMM)
    if (threadIdx.x < 64) {
        int f = threadIdx.x;
        float v = 0.f;
#pragma unroll
        for (int k = 0; k < 64; k++) v = fmaf(praw[k], __ldg(&W3[k * 64 + f]), v);
        pm[f] = (end > start) ? (v + __ldg(&b3[f])) : 0.f;
    }
    __syncthreads();
    // classifier: warp 0, thread jj computes hidden unit jj (32 units)
    if (threadIdx.x < 32) {
        int jj = threadIdx.x;
        float h = bc1[jj];
#pragma unroll
        for (int k = 0; k < 64; k++) h = fmaf(pm[k], __ldg(&Wc1[k * 32 + jj]), h);
        h = fmaxf(h, 0.f);
        float o0 = h * __ldg(&Wc2[jj * 2 + 0]);
        float o1 = h * __ldg(&Wc2[jj * 2 + 1]);
#pragma unroll
        for (int o = 16; o > 0; o >>= 1) {
            o0 += __shfl_down_sync(0xffffffffu, o0, o);
            o1 += __shfl_down_sync(0xffffffffu, o1, o);
        }
        if (jj == 0) {
            out[g * 2 + 0] = o0 + bc2[0];
            out[g * 2 + 1] = o1 + bc2[1];
        }
    }
}

// ---------------- launch ---------------------------------------------------
extern "C" void kernel_launch(void* const* d_in, const int* in_sizes, int n_in,
                              void* d_out, int out_size) {
    const float* x     = (const float*)d_in[0];
    const void*  ei    = d_in[1];
    const void*  batch = d_in[2];
    const float* W1 = (const float*)d_in[3];
    const float* b1 = (const float*)d_in[4];
    const float* W2 = (const float*)d_in[5];
    const float* b2 = (const float*)d_in[6];
    const float* W3 = (const float*)d_in[7];
    const float* b3 = (const float*)d_in[8];
    const float* Wc1 = (const float*)d_in[9];
    const float* bc1 = (const float*)d_in[10];
    const float* Wc2 = (const float*)d_in[11];
    const float* bc2 = (const float*)d_in[12];
    float* out = (float*)d_out;

    int N = in_sizes[0] / 128;
    int E = in_sizes[1] / 2;
    int G = out_size / 2;

    int nb = (N + 1023) / 1024;
    int gemm_blocks = (N + 127) / 128;
    int agg_blocks = (N + 7) / 8;

    // lazily created host-side objects (no device memory involved)
    static cudaStream_t s_gemm = nullptr;
    static cudaEvent_t ev_fork = nullptr, ev_join = nullptr;
    if (s_gemm == nullptr) {
        cudaStreamCreate(&s_gemm);
        cudaEventCreateWithFlags(&ev_fork, cudaEventDisableTiming);
        cudaEventCreateWithFlags(&ev_join, cudaEventDisableTiming);
    }

    // fork: GEMM1 (x @ W1, unprescaled) runs concurrent with the CSR build
    cudaEventRecord(ev_fork, 0);
    cudaStreamWaitEvent(s_gemm, ev_fork, 0);
    k_gemm<<<gemm_blocks, 256, 0, s_gemm>>>(x, 0, 0, W1, N, 128);
    cudaEventRecord(ev_join, s_gemm);

    // CSR build chain (d_cnt is zero on entry)
    k_detect<<<1, 1>>>(ei);
    k_count<<<(E + 255) / 256, 256>>>(ei, E);
    k_blocksum<<<nb, 256>>>(N);
    k_scanpart<<<1, 128>>>(nb, N, E);
    k_scanblock<<<nb, 1024>>>(N);
    k_fill<<<(E + 255) / 256, 256>>>(ei, E);

    // join, then conv1 aggregation (weighted: input h is unprescaled)
    cudaStreamWaitEvent(0, ev_join, 0);
    k_aggw<<<agg_blocks, 256>>>(b1, N, 1);                 // d_h -> d_g (g1)
    // conv2: GEMM prescaled, agg with post_scale (emits p2 = dis*g2)
    k_gemm<<<gemm_blocks, 256>>>(nullptr, 1, 1, W2, N, 64); // d_g -> d_h
    k_agg<<<agg_blocks, 256>>>(0, 1, b2, N, 1, 1);          // d_h -> d_g (p2)
    // conv3 aggregation only (W3/b3 deferred past the pool)
    k_agg<<<agg_blocks, 256>>>(1, 0, nullptr, N, 0, 0);     // d_g -> d_h (Â h2)

    // fused pool + W3/b3 + classifier
    k_poolcls<<<G, 256>>>(batch, N, W3, b3, Wc1, bc1, Wc2, bc2, out);
}